// round 15
// baseline (speedup 1.0000x reference)
#include <cuda_runtime.h>

// loss = ||F^T F - S^T S||_F^2 * 2^-38,  F/S = [ch=64, hw=8192] channel-major.
// SINGLE kernel, no grid barrier:
//   - 128 blocks x 512 threads (1/SM): 64x64 Gram-diff partial over 64 i's
//     (f32x2 packed FMA, padded SMEM, 2a x 4b tiles).
//   - Each thread RED.ADDs its 8 entries into the global 64x64 Gram diff
//     (16 KB, L2-resident, 4096 spread addresses).
//   - Last block (int-atomic elected) reads the Gram, squares, fixed-order
//     reduces, writes out, and re-zeros Gram + counter for the next replay.

#define CH    64
#define HW    8192
#define IPB   64
#define NBLK  (HW / IPB)   // 128
#define GELEM (CH * CH)    // 4096
#define PAD   68           // SMEM row stride: 272B, 16B-aligned rows

typedef unsigned long long u64;

__device__ float    g_gram[GELEM];   // zero at start; re-zeroed by last block
__device__ unsigned g_count;         // zero at start; reset by last block

__device__ __forceinline__ u64 fma2(u64 a, u64 b, u64 c) {
    u64 d;
    asm("fma.rn.f32x2 %0, %1, %2, %3;" : "=l"(d) : "l"(a), "l"(b), "l"(c));
    return d;
}
__device__ __forceinline__ u64 dup2(float x) {
    u64 r;
    asm("mov.b64 %0, {%1, %1};" : "=l"(r) : "f"(x));
    return r;
}

__global__ void __launch_bounds__(512, 1) gram_loss_kernel(const float* __restrict__ A,
                                                           const float* __restrict__ B,
                                                           float* __restrict__ out) {
    __shared__ __align__(16) float fsh[IPB][PAD];
    __shared__ __align__(16) float ssh[IPB][PAD];
    __shared__ float wsum[16];
    __shared__ bool  last;

    const int tid = threadIdx.x;
    const int bid = blockIdx.x;

    // ---------------- Phase 1: Gram-diff tile over 64 i's -------------------
    const int i0 = bid * IPB;
    const int c  = tid >> 3;        // channel 0..63
    const int g0 = tid & 7;         // i-group; thread covers g0 and g0+8

    const float4 fv0 = *reinterpret_cast<const float4*>(A + (size_t)c * HW + i0 + 4 * g0);
    const float4 fv1 = *reinterpret_cast<const float4*>(A + (size_t)c * HW + i0 + 4 * (g0 + 8));
    const float4 sv0 = *reinterpret_cast<const float4*>(B + (size_t)c * HW + i0 + 4 * g0);
    const float4 sv1 = *reinterpret_cast<const float4*>(B + (size_t)c * HW + i0 + 4 * (g0 + 8));
    {
        float f0[4] = {fv0.x, fv0.y, fv0.z, fv0.w};
        float f1[4] = {fv1.x, fv1.y, fv1.z, fv1.w};
        float s0[4] = {sv0.x, sv0.y, sv0.z, sv0.w};
        float s1[4] = {sv1.x, sv1.y, sv1.z, sv1.w};
#pragma unroll
        for (int k = 0; k < 4; ++k) {
            fsh[4 * g0 + k][c]       = f0[k];
            fsh[4 * (g0 + 8) + k][c] = f1[k];
            ssh[4 * g0 + k][c]       = s0[k];
            ssh[4 * (g0 + 8) + k][c] = s1[k];
        }
    }
    __syncthreads();

    const int ty = tid >> 4;   // a-pair (channels 2ty, 2ty+1)
    const int tx = tid & 15;   // b-quad

    u64 accf[4], accs[4];
#pragma unroll
    for (int b = 0; b < 4; ++b) { accf[b] = 0ull; accs[b] = 0ull; }

#pragma unroll 8
    for (int ii = 0; ii < IPB; ++ii) {
        float2     fa  = *reinterpret_cast<const float2*>(&fsh[ii][2 * ty]);
        ulonglong2 fbp = *reinterpret_cast<const ulonglong2*>(&fsh[ii][4 * tx]);
        float2     sa  = *reinterpret_cast<const float2*>(&ssh[ii][2 * ty]);
        ulonglong2 sbp = *reinterpret_cast<const ulonglong2*>(&ssh[ii][4 * tx]);

        u64 fd0 = dup2(fa.x), fd1 = dup2(fa.y);
        u64 sd0 = dup2(sa.x), sd1 = dup2(sa.y);

        accf[0] = fma2(fd0, fbp.x, accf[0]);
        accf[1] = fma2(fd0, fbp.y, accf[1]);
        accf[2] = fma2(fd1, fbp.x, accf[2]);
        accf[3] = fma2(fd1, fbp.y, accf[3]);
        accs[0] = fma2(sd0, sbp.x, accs[0]);
        accs[1] = fma2(sd0, sbp.y, accs[1]);
        accs[2] = fma2(sd1, sbp.x, accs[2]);
        accs[3] = fma2(sd1, sbp.y, accs[3]);
    }

    const u64 neg1 = dup2(-1.0f);
    u64 v0 = fma2(accs[0], neg1, accf[0]);  // row 2ty,   cols 4tx..4tx+1
    u64 v1 = fma2(accs[1], neg1, accf[1]);  // row 2ty,   cols 4tx+2..4tx+3
    u64 v2 = fma2(accs[2], neg1, accf[2]);  // row 2ty+1, cols 4tx..4tx+1
    u64 v3 = fma2(accs[3], neg1, accf[3]);  // row 2ty+1, cols 4tx+2..4tx+3

    float2 d0 = *reinterpret_cast<float2*>(&v0);
    float2 d1 = *reinterpret_cast<float2*>(&v1);
    float2 d2 = *reinterpret_cast<float2*>(&v2);
    float2 d3 = *reinterpret_cast<float2*>(&v3);

    // ---------------- RED.ADD into the global Gram diff ---------------------
    {
        float* r0 = g_gram + (2 * ty + 0) * CH + 4 * tx;
        float* r1 = g_gram + (2 * ty + 1) * CH + 4 * tx;
        atomicAdd(r0 + 0, d0.x);
        atomicAdd(r0 + 1, d0.y);
        atomicAdd(r0 + 2, d1.x);
        atomicAdd(r0 + 3, d1.y);
        atomicAdd(r1 + 0, d2.x);
        atomicAdd(r1 + 1, d2.y);
        atomicAdd(r1 + 2, d3.x);
        atomicAdd(r1 + 3, d3.y);
    }

    // ---------------- Last-block election ------------------------------------
    __threadfence();            // REDs visible before the counter bump
    __syncthreads();
    if (tid == 0) last = (atomicAdd(&g_count, 1u) == NBLK - 1);
    __syncthreads();
    if (!last) return;

    // ---------------- Final fold (one block, fixed order) --------------------
    __threadfence();            // acquire: all blocks' REDs ordered before this
    const float4 ga = __ldcg(reinterpret_cast<const float4*>(g_gram) + 2 * tid);
    const float4 gb = __ldcg(reinterpret_cast<const float4*>(g_gram) + 2 * tid + 1);
    float sq = ga.x * ga.x + ga.y * ga.y + ga.z * ga.z + ga.w * ga.w
             + gb.x * gb.x + gb.y * gb.y + gb.z * gb.z + gb.w * gb.w;

#pragma unroll
    for (int off = 16; off > 0; off >>= 1)
        sq += __shfl_down_sync(0xffffffffu, sq, off);
    if ((tid & 31) == 0) wsum[tid >> 5] = sq;
    __syncthreads();

    if (tid == 0) {
        float v = 0.0f;
#pragma unroll
        for (int k = 0; k < 16; ++k) v += wsum[k];
        out[0] = v * (1.0f / 274877906944.0f);  // * 2^-38 exact
    }

    // Re-zero Gram + counter for the next graph replay.
    const float4 z = make_float4(0.f, 0.f, 0.f, 0.f);
    reinterpret_cast<float4*>(g_gram)[2 * tid]     = z;
    reinterpret_cast<float4*>(g_gram)[2 * tid + 1] = z;
    if (tid == 0) g_count = 0u;
}

extern "C" void kernel_launch(void* const* d_in, const int* in_sizes, int n_in,
                              void* d_out, int out_size) {
    const float* A = (const float*)d_in[0];
    const float* B = (const float*)d_in[1];
    float* out = (float*)d_out;

    gram_loss_kernel<<<NBLK, 512>>>(A, B, out);
}

// round 16
// speedup vs baseline: 1.4147x; 1.4147x over previous
#include <cuda_runtime.h>

// loss = ||F^T F - S^T S||_F^2 * 2^-38,  F/S = [ch=64, hw=8192] channel-major.
// Two kernels; stream boundary is the only global sync.
//   K1 (unchanged from best): 128 blocks x 512 threads (1/SM): 64x64 Gram-diff
//       partial over 64 i's (f32x2 packed FMA, padded SMEM, 2a x 4b tiles).
//   K2 (new): 128 blocks x 256 threads. Block owns 32 Gram entries; thread
//       (row-group r = tid>>5, lane) sums 16 partials rows {r+8k} (fixed order,
//       16 independent fully-coalesced LDG.32). SMEM-fold 8 row-groups, square,
//       warp-reduce -> g_bp[bid]; last block (atomic-elected) folds 128 sums.

#define CH    64
#define HW    8192
#define IPB   64
#define NBLK  (HW / IPB)   // 128 partial Gram matrices
#define GELEM (CH * CH)    // 4096
#define PAD   68           // K1 SMEM row stride: 272B, 16B-aligned rows

typedef unsigned long long u64;

__device__ float    g_partials[NBLK * GELEM];
__device__ float    g_bp[128];
__device__ unsigned g_count;   // zero-init; reset by last K2 block each call

__device__ __forceinline__ u64 fma2(u64 a, u64 b, u64 c) {
    u64 d;
    asm("fma.rn.f32x2 %0, %1, %2, %3;" : "=l"(d) : "l"(a), "l"(b), "l"(c));
    return d;
}
__device__ __forceinline__ u64 dup2(float x) {
    u64 r;
    asm("mov.b64 %0, {%1, %1};" : "=l"(r) : "f"(x));
    return r;
}

__global__ void __launch_bounds__(512, 1) gram_kernel(const float* __restrict__ A,
                                                      const float* __restrict__ B) {
    __shared__ __align__(16) float fsh[IPB][PAD];
    __shared__ __align__(16) float ssh[IPB][PAD];

    const int tid = threadIdx.x;
    const int bid = blockIdx.x;
    const int i0  = bid * IPB;
    const int c   = tid >> 3;       // channel 0..63
    const int g0  = tid & 7;        // i-group; thread covers g0 and g0+8

    const float4 fv0 = *reinterpret_cast<const float4*>(A + (size_t)c * HW + i0 + 4 * g0);
    const float4 fv1 = *reinterpret_cast<const float4*>(A + (size_t)c * HW + i0 + 4 * (g0 + 8));
    const float4 sv0 = *reinterpret_cast<const float4*>(B + (size_t)c * HW + i0 + 4 * g0);
    const float4 sv1 = *reinterpret_cast<const float4*>(B + (size_t)c * HW + i0 + 4 * (g0 + 8));
    {
        float f0[4] = {fv0.x, fv0.y, fv0.z, fv0.w};
        float f1[4] = {fv1.x, fv1.y, fv1.z, fv1.w};
        float s0[4] = {sv0.x, sv0.y, sv0.z, sv0.w};
        float s1[4] = {sv1.x, sv1.y, sv1.z, sv1.w};
#pragma unroll
        for (int k = 0; k < 4; ++k) {
            fsh[4 * g0 + k][c]       = f0[k];
            fsh[4 * (g0 + 8) + k][c] = f1[k];
            ssh[4 * g0 + k][c]       = s0[k];
            ssh[4 * (g0 + 8) + k][c] = s1[k];
        }
    }
    __syncthreads();

    const int ty = tid >> 4;   // a-pair (channels 2ty, 2ty+1)
    const int tx = tid & 15;   // b-quad

    u64 accf[4], accs[4];
#pragma unroll
    for (int b = 0; b < 4; ++b) { accf[b] = 0ull; accs[b] = 0ull; }

#pragma unroll 8
    for (int ii = 0; ii < IPB; ++ii) {
        float2     fa  = *reinterpret_cast<const float2*>(&fsh[ii][2 * ty]);
        ulonglong2 fbp = *reinterpret_cast<const ulonglong2*>(&fsh[ii][4 * tx]);
        float2     sa  = *reinterpret_cast<const float2*>(&ssh[ii][2 * ty]);
        ulonglong2 sbp = *reinterpret_cast<const ulonglong2*>(&ssh[ii][4 * tx]);

        u64 fd0 = dup2(fa.x), fd1 = dup2(fa.y);
        u64 sd0 = dup2(sa.x), sd1 = dup2(sa.y);

        accf[0] = fma2(fd0, fbp.x, accf[0]);
        accf[1] = fma2(fd0, fbp.y, accf[1]);
        accf[2] = fma2(fd1, fbp.x, accf[2]);
        accf[3] = fma2(fd1, fbp.y, accf[3]);
        accs[0] = fma2(sd0, sbp.x, accs[0]);
        accs[1] = fma2(sd0, sbp.y, accs[1]);
        accs[2] = fma2(sd1, sbp.x, accs[2]);
        accs[3] = fma2(sd1, sbp.y, accs[3]);
    }

    const u64 neg1 = dup2(-1.0f);
    u64 v0 = fma2(accs[0], neg1, accf[0]);
    u64 v1 = fma2(accs[1], neg1, accf[1]);
    u64 v2 = fma2(accs[2], neg1, accf[2]);
    u64 v3 = fma2(accs[3], neg1, accf[3]);

    float* p = g_partials + (size_t)bid * GELEM;
    float2 d0 = *reinterpret_cast<float2*>(&v0);
    float2 d1 = *reinterpret_cast<float2*>(&v1);
    float2 d2 = *reinterpret_cast<float2*>(&v2);
    float2 d3 = *reinterpret_cast<float2*>(&v3);
    *reinterpret_cast<float4*>(p + (2 * ty + 0) * CH + 4 * tx) =
        make_float4(d0.x, d0.y, d1.x, d1.y);
    *reinterpret_cast<float4*>(p + (2 * ty + 1) * CH + 4 * tx) =
        make_float4(d2.x, d2.y, d3.x, d3.y);
}

__global__ void __launch_bounds__(256) reduce_kernel(float* __restrict__ out) {
    // Block owns 32 Gram entries: e = bid*32 + lane.
    // Thread (r = tid>>5 in 0..7, lane) sums partial rows {r, r+8, ..., r+120}.
    __shared__ float sh[8][32];
    __shared__ bool  last;

    const int tid  = threadIdx.x;
    const int bid  = blockIdx.x;
    const int lane = tid & 31;
    const int r    = tid >> 5;            // row-group 0..7
    const int e    = bid * 32 + lane;     // Gram entry 0..4095

    float s = 0.0f;
#pragma unroll
    for (int k = 0; k < 16; ++k)
        s += g_partials[(size_t)(r + 8 * k) * GELEM + e];
    sh[r][lane] = s;
    __syncthreads();

    if (tid < 32) {
        float tot = sh[0][tid];
#pragma unroll
        for (int j = 1; j < 8; ++j) tot += sh[j][tid];
        float sq = tot * tot;
#pragma unroll
        for (int off = 16; off > 0; off >>= 1)
            sq += __shfl_down_sync(0xffffffffu, sq, off);
        if (tid == 0) {
            g_bp[bid] = sq;
            __threadfence();
            last = (atomicAdd(&g_count, 1u) == 127u);
        }
    }
    __syncthreads();

    if (last && tid < 32) {
        __threadfence();
        volatile float* vb = g_bp;
        float v = vb[tid] + vb[tid + 32] + vb[tid + 64] + vb[tid + 96];
#pragma unroll
        for (int off = 16; off > 0; off >>= 1)
            v += __shfl_down_sync(0xffffffffu, v, off);
        if (tid == 0) {
            out[0] = v * (1.0f / 274877906944.0f);  // * 2^-38 exact
            g_count = 0u;                           // reset for next replay
        }
    }
}

extern "C" void kernel_launch(void* const* d_in, const int* in_sizes, int n_in,
                              void* d_out, int out_size) {
    const float* A = (const float*)d_in[0];
    const float* B = (const float*)d_in[1];
    float* out = (float*)d_out;

    gram_kernel<<<NBLK, 512>>>(A, B);
    reduce_kernel<<<128, 256>>>(out);
}

// round 17
// speedup vs baseline: 1.5127x; 1.0693x over previous
#include <cuda_runtime.h>

// loss = ||F^T F - S^T S||_F^2 * 2^-38,  F/S = [ch=64, hw=8192] channel-major.
// Two kernels; stream boundary is the only global sync.
//   K1: 256 blocks x 256 threads (2/SM), IPB=32: 64x64 Gram-diff partial,
//       4a x 4b register tile per thread (16 fma2/iter, 4 LDS.128/iter).
//   K2: 128 blocks x 512 threads: sum 256 partials per Gram entry (fixed order,
//       fully coalesced), square, block-sum; last block (atomic-elected) folds.

#define CH    64
#define HW    8192
#define IPB   32
#define NBLK  (HW / IPB)   // 256 partial Gram matrices
#define GELEM (CH * CH)    // 4096
#define PAD   68           // SMEM row stride: 272B, 16B-aligned rows

typedef unsigned long long u64;

__device__ float    g_partials[NBLK * GELEM];
__device__ float    g_bp[128];
__device__ unsigned g_count;   // zero-init; reset by last K2 block each call

__device__ __forceinline__ u64 fma2(u64 a, u64 b, u64 c) {
    u64 d;
    asm("fma.rn.f32x2 %0, %1, %2, %3;" : "=l"(d) : "l"(a), "l"(b), "l"(c));
    return d;
}
__device__ __forceinline__ u64 dup2(float x) {
    u64 r;
    asm("mov.b64 %0, {%1, %1};" : "=l"(r) : "f"(x));
    return r;
}

__global__ void __launch_bounds__(256, 2) gram_kernel(const float* __restrict__ A,
                                                      const float* __restrict__ B) {
    __shared__ __align__(16) float fsh[IPB][PAD];
    __shared__ __align__(16) float ssh[IPB][PAD];

    const int tid = threadIdx.x;
    const int bid = blockIdx.x;
    const int i0  = bid * IPB;

    // Stage 64ch x 32i per matrix: 512 float4 stores; thread does idx, idx+256.
#pragma unroll
    for (int r = 0; r < 2; ++r) {
        const int idx = r * 256 + tid;   // 0..511
        const int c   = idx >> 3;        // channel 0..63
        const int g   = idx & 7;         // i-group 0..7
        const float4 fv = *reinterpret_cast<const float4*>(A + (size_t)c * HW + i0 + 4 * g);
        const float4 sv = *reinterpret_cast<const float4*>(B + (size_t)c * HW + i0 + 4 * g);
        float fvals[4] = {fv.x, fv.y, fv.z, fv.w};
        float svals[4] = {sv.x, sv.y, sv.z, sv.w};
#pragma unroll
        for (int k = 0; k < 4; ++k) {
            fsh[4 * g + k][c] = fvals[k];
            ssh[4 * g + k][c] = svals[k];
        }
    }
    __syncthreads();

    // ty -> a-quad (channels 4ty..4ty+3), tx -> b-quad (channels 4tx..4tx+3).
    const int ty = tid >> 4;
    const int tx = tid & 15;

    u64 accf[4][2], accs[4][2];
#pragma unroll
    for (int a = 0; a < 4; ++a) {
        accf[a][0] = accf[a][1] = 0ull;
        accs[a][0] = accs[a][1] = 0ull;
    }

#pragma unroll 8
    for (int ii = 0; ii < IPB; ++ii) {
        float4     fa  = *reinterpret_cast<const float4*>(&fsh[ii][4 * ty]);
        ulonglong2 fbp = *reinterpret_cast<const ulonglong2*>(&fsh[ii][4 * tx]);
        float4     sa  = *reinterpret_cast<const float4*>(&ssh[ii][4 * ty]);
        ulonglong2 sbp = *reinterpret_cast<const ulonglong2*>(&ssh[ii][4 * tx]);

        u64 fd[4] = {dup2(fa.x), dup2(fa.y), dup2(fa.z), dup2(fa.w)};
        u64 sd[4] = {dup2(sa.x), dup2(sa.y), dup2(sa.z), dup2(sa.w)};

#pragma unroll
        for (int a = 0; a < 4; ++a) {
            accf[a][0] = fma2(fd[a], fbp.x, accf[a][0]);
            accf[a][1] = fma2(fd[a], fbp.y, accf[a][1]);
            accs[a][0] = fma2(sd[a], sbp.x, accs[a][0]);
            accs[a][1] = fma2(sd[a], sbp.y, accs[a][1]);
        }
    }

    // D = F-acc - S-acc, write 4 rows x 4 cols.
    const u64 neg1 = dup2(-1.0f);
    float* p = g_partials + (size_t)bid * GELEM;
#pragma unroll
    for (int a = 0; a < 4; ++a) {
        u64 v0 = fma2(accs[a][0], neg1, accf[a][0]);
        u64 v1 = fma2(accs[a][1], neg1, accf[a][1]);
        float2 d0 = *reinterpret_cast<float2*>(&v0);
        float2 d1 = *reinterpret_cast<float2*>(&v1);
        *reinterpret_cast<float4*>(p + (4 * ty + a) * CH + 4 * tx) =
            make_float4(d0.x, d0.y, d1.x, d1.y);
    }
}

__global__ void __launch_bounds__(512) reduce_kernel(float* __restrict__ out) {
    // Block owns 32 Gram entries: e = bid*32 + lane.
    // Thread (r = tid>>5 in 0..15, lane) sums partial rows {r + 16k}, k<16.
    __shared__ float sh[16][32];
    __shared__ bool  last;

    const int tid  = threadIdx.x;
    const int bid  = blockIdx.x;
    const int lane = tid & 31;
    const int r    = tid >> 5;            // row-group 0..15
    const int e    = bid * 32 + lane;     // Gram entry 0..4095

    float s = 0.0f;
#pragma unroll
    for (int k = 0; k < 16; ++k)
        s += g_partials[(size_t)(r + 16 * k) * GELEM + e];
    sh[r][lane] = s;
    __syncthreads();

    if (tid < 32) {
        float tot = sh[0][tid];
#pragma unroll
        for (int j = 1; j < 16; ++j) tot += sh[j][tid];
        float sq = tot * tot;
#pragma unroll
        for (int off = 16; off > 0; off >>= 1)
            sq += __shfl_down_sync(0xffffffffu, sq, off);
        if (tid == 0) {
            g_bp[bid] = sq;
            __threadfence();
            last = (atomicAdd(&g_count, 1u) == 127u);
        }
    }
    __syncthreads();

    if (last && tid < 32) {
        __threadfence();
        volatile float* vb = g_bp;
        float v = vb[tid] + vb[tid + 32] + vb[tid + 64] + vb[tid + 96];
#pragma unroll
        for (int off = 16; off > 0; off >>= 1)
            v += __shfl_down_sync(0xffffffffu, v, off);
        if (tid == 0) {
            out[0] = v * (1.0f / 274877906944.0f);  // * 2^-38 exact
            g_count = 0u;                           // reset for next replay
        }
    }
}

extern "C" void kernel_launch(void* const* d_in, const int* in_sizes, int n_in,
                              void* d_out, int out_size) {
    const float* A = (const float*)d_in[0];
    const float* B = (const float*)d_in[1];
    float* out = (float*)d_out;

    gram_kernel<<<NBLK, 256>>>(A, B);
    reduce_kernel<<<128, 512>>>(out);
}